// round 4
// baseline (speedup 1.0000x reference)
#include <cuda_runtime.h>

#define DIN   256
#define DOUT  64
#define HEADS 4
#define SLOPE 0.2f
#define MAXN  50000
#define MAXE  1600000

// Device-global scratch (no allocations allowed).
__device__ float  g_hW[(size_t)MAXN * DOUT];
__device__ float4 g_s[MAXN];
__device__ float4 g_d[MAXN];
__device__ float4 g_ex[MAXE];
__device__ int    g_ptr[MAXN + 1];

// ---------------------------------------------------------------------------
// Kernel 1: hW = h @ W + b   (tiled 64x64, BK=64, 256 threads, 4x4 microtile)
// ---------------------------------------------------------------------------
__global__ void gemm_kernel(const float* __restrict__ A,
                            const float* __restrict__ W,
                            const float* __restrict__ bias, int n) {
    __shared__ float As[64][68];
    __shared__ float Bs[64][64];
    int tid  = threadIdx.x;        // 256 threads
    int row0 = blockIdx.x * 64;
    int ty   = tid >> 4;
    int tx   = tid & 15;

    float acc[4][4];
#pragma unroll
    for (int i = 0; i < 4; i++)
#pragma unroll
        for (int j = 0; j < 4; j++) acc[i][j] = 0.f;

    for (int k0 = 0; k0 < DIN; k0 += 64) {
#pragma unroll
        for (int q = 0; q < 4; q++) {
            int f  = tid + 256 * q;
            int rr = f >> 4;
            int cv = f & 15;
            int gr = row0 + rr;
            float4 v = (gr < n)
                ? *(const float4*)(A + (size_t)gr * DIN + k0 + cv * 4)
                : make_float4(0.f, 0.f, 0.f, 0.f);
            *(float4*)&As[rr][cv * 4] = v;
            float4 w = *(const float4*)(W + (size_t)(k0 + rr) * DOUT + cv * 4);
            *(float4*)&Bs[rr][cv * 4] = w;
        }
        __syncthreads();
#pragma unroll
        for (int kk = 0; kk < 64; kk++) {
            float a0 = As[ty * 4 + 0][kk];
            float a1 = As[ty * 4 + 1][kk];
            float a2 = As[ty * 4 + 2][kk];
            float a3 = As[ty * 4 + 3][kk];
            float4 bv = *(float4*)&Bs[kk][tx * 4];
            acc[0][0] += a0 * bv.x; acc[0][1] += a0 * bv.y; acc[0][2] += a0 * bv.z; acc[0][3] += a0 * bv.w;
            acc[1][0] += a1 * bv.x; acc[1][1] += a1 * bv.y; acc[1][2] += a1 * bv.z; acc[1][3] += a1 * bv.w;
            acc[2][0] += a2 * bv.x; acc[2][1] += a2 * bv.y; acc[2][2] += a2 * bv.z; acc[2][3] += a2 * bv.w;
            acc[3][0] += a3 * bv.x; acc[3][1] += a3 * bv.y; acc[3][2] += a3 * bv.z; acc[3][3] += a3 * bv.w;
        }
        __syncthreads();
    }

    float4 bv = *(const float4*)(bias + tx * 4);
#pragma unroll
    for (int i = 0; i < 4; i++) {
        int gr = row0 + ty * 4 + i;
        if (gr < n) {
            float4 o = make_float4(acc[i][0] + bv.x, acc[i][1] + bv.y,
                                   acc[i][2] + bv.z, acc[i][3] + bv.w);
            *(float4*)(g_hW + (size_t)gr * DOUT + tx * 4) = o;
        }
    }
}

// ---------------------------------------------------------------------------
// Kernel 2: per-node logits s[h] = hW[n].a_src[h], d[h] = hW[n].a_dst[h]
// ---------------------------------------------------------------------------
__global__ void attn_kernel(const float* __restrict__ a_src,
                            const float* __restrict__ a_dst, int n) {
    int w    = (blockIdx.x * blockDim.x + threadIdx.x) >> 5;
    int lane = threadIdx.x & 31;
    if (w >= n) return;

    float2 hv = *(const float2*)(g_hW + (size_t)w * DOUT + 2 * lane);
    float sv[HEADS], dv[HEADS];
#pragma unroll
    for (int h = 0; h < HEADS; h++) {
        float2 as = __ldg((const float2*)(a_src + h * DOUT + 2 * lane));
        float2 ad = __ldg((const float2*)(a_dst + h * DOUT + 2 * lane));
        sv[h] = hv.x * as.x + hv.y * as.y;
        dv[h] = hv.x * ad.x + hv.y * ad.y;
    }
#pragma unroll
    for (int o = 16; o; o >>= 1) {
#pragma unroll
        for (int h = 0; h < HEADS; h++) {
            sv[h] += __shfl_xor_sync(0xffffffffu, sv[h], o);
            dv[h] += __shfl_xor_sync(0xffffffffu, dv[h], o);
        }
    }
    if (lane == 0) {
        g_s[w] = make_float4(sv[0], sv[1], sv[2], sv[3]);
        g_d[w] = make_float4(dv[0], dv[1], dv[2], dv[3]);
    }
}

// ---------------------------------------------------------------------------
// Kernel 3: CSR row_ptr from sorted row[] (boundary fill).
// ---------------------------------------------------------------------------
__global__ void ptr_kernel(const int* __restrict__ row, int e, int n) {
    int i = blockIdx.x * blockDim.x + threadIdx.x;
    if (i > e) return;
    int cur  = (i < e) ? row[i] : n;
    int prev = (i > 0) ? row[i - 1] : -1;
    for (int r = prev + 1; r <= cur; r++) g_ptr[r] = i;
}

// ---------------------------------------------------------------------------
// Kernel 4: per-edge unnormalized weights, one thread per edge.
// ex[j] = exp(lrelu(s[row[j]] + d[col[j]])), all 4 heads at once.
// (No max subtraction: logits are O(1) here, softmax is shift-invariant.)
// ---------------------------------------------------------------------------
__device__ __forceinline__ float lrelu(float x) { return fmaxf(x, SLOPE * x); }

__global__ void exp_kernel(const int* __restrict__ row,
                           const int* __restrict__ col, int e) {
    int i = blockIdx.x * blockDim.x + threadIdx.x;
    if (i >= e) return;
    float4 s = g_s[__ldg(row + i)];
    float4 d = g_d[__ldg(col + i)];
    float4 ex;
    ex.x = __expf(lrelu(s.x + d.x));
    ex.y = __expf(lrelu(s.y + d.y));
    ex.z = __expf(lrelu(s.z + d.z));
    ex.w = __expf(lrelu(s.w + d.w));
    g_ex[i] = ex;
}

// ---------------------------------------------------------------------------
// Kernel 5: single-scan weighted aggregation, one warp per row.
// out_r = (sum_j ex_j * hW[col_j]) / (sum_j ex_j)  -- normalize at the end.
// Half-warp split: lanes 0-15 even edge, lanes 16-31 odd edge; float4
// feature loads; shuffle-combine halves, then one divide.
// ---------------------------------------------------------------------------
__global__ void edge_kernel(const int* __restrict__ col,
                            float* __restrict__ out, int n) {
    int r    = (blockIdx.x * blockDim.x + threadIdx.x) >> 5;
    int lane = threadIdx.x & 31;
    if (r >= n) return;

    int start = g_ptr[r];
    int end   = g_ptr[r + 1];
    int half  = lane >> 4;
    int l16   = lane & 15;

    float4 acc0 = make_float4(0.f, 0.f, 0.f, 0.f);
    float4 acc1 = acc0, acc2 = acc0, acc3 = acc0;
    float dn0 = 0.f, dn1 = 0.f, dn2 = 0.f, dn3 = 0.f;
    const float4* hW4 = (const float4*)g_hW;   // 16 float4 per node row

    int deg = end - start;
    int e2  = start + (deg & ~1);
#pragma unroll 2
    for (int j = start; j < e2; j += 2) {
        int je = j + half;
        int c  = __ldg(col + je);
        float4 ex = g_ex[je];
        float4 hv = hW4[(size_t)c * 16 + l16];
        dn0 += ex.x; dn1 += ex.y; dn2 += ex.z; dn3 += ex.w;
        acc0.x += ex.x * hv.x; acc0.y += ex.x * hv.y; acc0.z += ex.x * hv.z; acc0.w += ex.x * hv.w;
        acc1.x += ex.y * hv.x; acc1.y += ex.y * hv.y; acc1.z += ex.y * hv.z; acc1.w += ex.y * hv.w;
        acc2.x += ex.z * hv.x; acc2.y += ex.z * hv.y; acc2.z += ex.z * hv.z; acc2.w += ex.z * hv.w;
        acc3.x += ex.w * hv.x; acc3.y += ex.w * hv.y; acc3.z += ex.w * hv.z; acc3.w += ex.w * hv.w;
    }
    if ((deg & 1) && half == 0) {   // last odd edge, lower half only
        int je = e2;
        int c  = __ldg(col + je);
        float4 ex = g_ex[je];
        float4 hv = hW4[(size_t)c * 16 + l16];
        dn0 += ex.x; dn1 += ex.y; dn2 += ex.z; dn3 += ex.w;
        acc0.x += ex.x * hv.x; acc0.y += ex.x * hv.y; acc0.z += ex.x * hv.z; acc0.w += ex.x * hv.w;
        acc1.x += ex.y * hv.x; acc1.y += ex.y * hv.y; acc1.z += ex.y * hv.z; acc1.w += ex.y * hv.w;
        acc2.x += ex.z * hv.x; acc2.y += ex.z * hv.y; acc2.z += ex.z * hv.z; acc2.w += ex.z * hv.w;
        acc3.x += ex.w * hv.x; acc3.y += ex.w * hv.y; acc3.z += ex.w * hv.z; acc3.w += ex.w * hv.w;
    }

    // Combine the two half-warp partial sums (lane L += lane L+16).
    acc0.x += __shfl_down_sync(0xffffffffu, acc0.x, 16);
    acc0.y += __shfl_down_sync(0xffffffffu, acc0.y, 16);
    acc0.z += __shfl_down_sync(0xffffffffu, acc0.z, 16);
    acc0.w += __shfl_down_sync(0xffffffffu, acc0.w, 16);
    acc1.x += __shfl_down_sync(0xffffffffu, acc1.x, 16);
    acc1.y += __shfl_down_sync(0xffffffffu, acc1.y, 16);
    acc1.z += __shfl_down_sync(0xffffffffu, acc1.z, 16);
    acc1.w += __shfl_down_sync(0xffffffffu, acc1.w, 16);
    acc2.x += __shfl_down_sync(0xffffffffu, acc2.x, 16);
    acc2.y += __shfl_down_sync(0xffffffffu, acc2.y, 16);
    acc2.z += __shfl_down_sync(0xffffffffu, acc2.z, 16);
    acc2.w += __shfl_down_sync(0xffffffffu, acc2.w, 16);
    acc3.x += __shfl_down_sync(0xffffffffu, acc3.x, 16);
    acc3.y += __shfl_down_sync(0xffffffffu, acc3.y, 16);
    acc3.z += __shfl_down_sync(0xffffffffu, acc3.z, 16);
    acc3.w += __shfl_down_sync(0xffffffffu, acc3.w, 16);
    dn0 += __shfl_down_sync(0xffffffffu, dn0, 16);
    dn1 += __shfl_down_sync(0xffffffffu, dn1, 16);
    dn2 += __shfl_down_sync(0xffffffffu, dn2, 16);
    dn3 += __shfl_down_sync(0xffffffffu, dn3, 16);

    if (half == 0) {
        float i0 = 1.f / dn0, i1 = 1.f / dn1, i2 = 1.f / dn2, i3 = 1.f / dn3;
        acc0.x *= i0; acc0.y *= i0; acc0.z *= i0; acc0.w *= i0;
        acc1.x *= i1; acc1.y *= i1; acc1.z *= i1; acc1.w *= i1;
        acc2.x *= i2; acc2.y *= i2; acc2.z *= i2; acc2.w *= i2;
        acc3.x *= i3; acc3.y *= i3; acc3.z *= i3; acc3.w *= i3;
        float4* o4 = (float4*)(out + (size_t)r * 256);
        o4[l16]      = acc0;
        o4[16 + l16] = acc1;
        o4[32 + l16] = acc2;
        o4[48 + l16] = acc3;
    }
}

// ---------------------------------------------------------------------------
extern "C" void kernel_launch(void* const* d_in, const int* in_sizes, int n_in,
                              void* d_out, int out_size) {
    const float* h     = (const float*)d_in[0];
    const float* W     = (const float*)d_in[1];
    const float* b     = (const float*)d_in[2];
    const float* a_src = (const float*)d_in[3];
    const float* a_dst = (const float*)d_in[4];
    const int*   row   = (const int*)d_in[5];
    const int*   col   = (const int*)d_in[6];
    float*       out   = (float*)d_out;

    int n = in_sizes[0] / DIN;
    int e = in_sizes[5];

    gemm_kernel<<<(n + 63) / 64, 256>>>(h, W, b, n);
    attn_kernel<<<(n + 7) / 8, 256>>>(a_src, a_dst, n);
    ptr_kernel<<<(e + 1 + 255) / 256, 256>>>(row, e, n);
    exp_kernel<<<(e + 255) / 256, 256>>>(row, col, e);
    edge_kernel<<<(n + 7) / 8, 256>>>(col, out, n);
}